// round 12
// baseline (speedup 1.0000x reference)
#include <cuda_runtime.h>

// Problem constants
#define S_LEN   512
#define HDIM    1024
#define BATCH   64
#define IDIM    1024
#define M_TOT   (BATCH * S_LEN)          // 32768
#define OUT_TAIL (BATCH * S_LEN * HDIM)  // offset of h_last region in d_out

typedef unsigned long long u64;

// ---- packed f32x2 helpers (SASS FFMA2 path, PTX-only) ----
__device__ __forceinline__ u64 pack2(float lo, float hi) {
    u64 r;
    asm("mov.b64 %0, {%1, %2};" : "=l"(r) : "f"(lo), "f"(hi));
    return r;
}
__device__ __forceinline__ void unpack2(float& lo, float& hi, u64 v) {
    asm("mov.b64 {%0, %1}, %2;" : "=f"(lo), "=f"(hi) : "l"(v));
}
__device__ __forceinline__ void fma2(u64& d, u64 a, u64 b) {
    asm("fma.rn.f32x2 %0, %1, %2, %0;" : "+l"(d) : "l"(a), "l"(b));
}

// ====================================================================
// Kernel 1: input projection GEMM with f32x2 accumulation (unchanged)
// ====================================================================
__global__ void __launch_bounds__(256) xproj_kernel(
    const float* __restrict__ A,
    const float* __restrict__ W,
    const float* __restrict__ bih,
    const float* __restrict__ bhh,
    float* __restrict__ C)
{
    __shared__ float As[16][132];
    __shared__ float Bs[16][132];

    const int tid = threadIdx.x;
    const int tx  = tid & 15;
    const int ty  = tid >> 4;
    const int m0  = blockIdx.y * 128;
    const int n0  = blockIdx.x * 128;

    u64 acc2[8][4];
#pragma unroll
    for (int i = 0; i < 8; i++)
#pragma unroll
        for (int p = 0; p < 4; p++) acc2[i][p] = 0ull;

    const float4* A4 = (const float4*)A;
    const float4* W4 = (const float4*)W;

    for (int k0 = 0; k0 < IDIM; k0 += 16) {
        const int kq = k0 >> 2;
#pragma unroll
        for (int q = 0; q < 2; q++) {
            int f  = q * 256 + tid;
            int r  = f >> 2;
            int c4 = f & 3;
            float4 av = A4[(size_t)(m0 + r) * 256 + kq + c4];
            As[c4 * 4 + 0][r] = av.x;
            As[c4 * 4 + 1][r] = av.y;
            As[c4 * 4 + 2][r] = av.z;
            As[c4 * 4 + 3][r] = av.w;
            float4 bv = W4[(size_t)(n0 + r) * 256 + kq + c4];
            Bs[c4 * 4 + 0][r] = bv.x;
            Bs[c4 * 4 + 1][r] = bv.y;
            Bs[c4 * 4 + 2][r] = bv.z;
            Bs[c4 * 4 + 3][r] = bv.w;
        }
        __syncthreads();

#pragma unroll
        for (int kk = 0; kk < 16; kk++) {
            float ra[8];
            *(float4*)&ra[0] = *(const float4*)&As[kk][ty * 4];
            *(float4*)&ra[4] = *(const float4*)&As[kk][64 + ty * 4];
            ulonglong2 rb0 = *(const ulonglong2*)&Bs[kk][tx * 4];
            ulonglong2 rb1 = *(const ulonglong2*)&Bs[kk][64 + tx * 4];
#pragma unroll
            for (int i = 0; i < 8; i++) {
                u64 rap = pack2(ra[i], ra[i]);
                fma2(acc2[i][0], rap, rb0.x);
                fma2(acc2[i][1], rap, rb0.y);
                fma2(acc2[i][2], rap, rb1.x);
                fma2(acc2[i][3], rap, rb1.y);
            }
        }
        __syncthreads();
    }

    float bsum[8];
#pragma unroll
    for (int j = 0; j < 8; j++) {
        int n = n0 + ((j < 4) ? (tx * 4 + j) : (64 + tx * 4 + (j - 4)));
        bsum[j] = bih[n] + bhh[n];
    }
#pragma unroll
    for (int i = 0; i < 8; i++) {
        int m = m0 + ((i < 4) ? (ty * 4 + i) : (64 + ty * 4 + (i - 4)));
        float c[8];
        unpack2(c[0], c[1], acc2[i][0]);
        unpack2(c[2], c[3], acc2[i][1]);
        unpack2(c[4], c[5], acc2[i][2]);
        unpack2(c[6], c[7], acc2[i][3]);
        float4 v0, v1;
        v0.x = c[0] + bsum[0]; v0.y = c[1] + bsum[1];
        v0.z = c[2] + bsum[2]; v0.w = c[3] + bsum[3];
        v1.x = c[4] + bsum[4]; v1.y = c[5] + bsum[5];
        v1.z = c[6] + bsum[6]; v1.w = c[7] + bsum[7];
        *(float4*)&C[(size_t)m * HDIM + n0 + tx * 4]      = v0;
        *(float4*)&C[(size_t)m * HDIM + n0 + 64 + tx * 4] = v1;
    }
}

// ====================================================================
// Kernel 2: persistent recurrence, v11 (R11 inner code at occ=25%).
//   128 CTAs = 4 groups x 32 CTAs, 512 threads (16 warps, 4/SMSP).
//   Warp w owns K-chunk [w*64,+64): warp-private pipelined staging,
//   4j x 4b thread tile, 16 dot iters. Two-phase partial reduction
//   (warps 8-15 add into warps 0-7's arrays) to fit SMEM.
// ====================================================================
#define WSTR 1028                     // hsm/Wsm row stride (floats)
#define RSTR 40                       // partials: conflict-free pattern
#define RED_WSZ (16 * RSTR)           // 640 floats per array
#define SM_H   (32 * WSTR)
#define SM_RED (48 * WSTR)
#define REC_SMEM_FLOATS (48 * WSTR + 8 * RED_WSZ)   // 217.9 KB
#define REC_SMEM_BYTES  (REC_SMEM_FLOATS * 4)

__device__ unsigned g_cnt[4];
__device__ volatile unsigned g_phase[4];

__global__ void __launch_bounds__(512, 1) rec_kernel(
    const float* __restrict__ h0,
    const float* __restrict__ Whh,
    float* out)
{
    extern __shared__ float sm[];
    float* Wsm = sm;              // [32][WSTR]
    float* hsm = sm + SM_H;       // [16][WSTR] (columns warp-disjoint)
    float* red = sm + SM_RED;     // [8][16*RSTR]

    const int cta = blockIdx.x;
    const int grp = cta >> 5;        // 0..3 batch group
    const int gc  = cta & 31;        // 0..31 within group
    const int j0  = gc * 32;
    const int b0g = grp * 16;
    const int tid = threadIdx.x;
    const int w   = tid >> 5;        // warp 0..15: owns K chunk [w*64, +64)
    const int l   = tid & 31;
    const int jj  = l & 7;           // j rows: jj, jj+8, jj+16, jj+24
    const int bb  = l >> 3;          // b rows: bb, bb+4, bb+8, bb+12

    // ---- load W_hh rows [j0, j0+32) into SMEM once ----
    {
        const float4* W4 = (const float4*)Whh;
        for (int i = tid; i < 32 * 256; i += 512) {
            int r = i >> 8, c = i & 255;
            *(float4*)&Wsm[r * WSTR + c * 4] = W4[(size_t)(j0 + r) * 256 + c];
        }
    }
    __syncthreads();

    // dot-loop base pointers (k-chunk offset w*64 floats = 16 ull2)
    const ulonglong2* wp[4];
    const ulonglong2* hp[4];
#pragma unroll
    for (int i = 0; i < 4; i++)
        wp[i] = (const ulonglong2*)(Wsm + (jj + 8 * i) * WSTR + w * 64);
#pragma unroll
    for (int m = 0; m < 4; m++)
        hp[m] = (const ulonglong2*)(hsm + (bb + 4 * m) * WSTR + w * 64);

    // reduce-phase mapping: 1 output/thread
    const int rb = tid >> 5;          // 0..15 (batch row)
    const int rj = tid & 31;          // 0..31 (neuron)
    const int bglob_r = b0g + rb;
    const int jglob_r = j0 + rj;

    unsigned my_phase = 0;

    for (int t = 0; t < S_LEN; t++) {
        // ---- xp prefetch (addr written only by this thread at step end) ----
        const size_t oxp = ((size_t)bglob_r * S_LEN + t) * HDIM + jglob_r;
        float xv = out[oxp];

        // ---- warp-private stage of k-slice (16 rows x 16 f4-cols), 2 chunks ----
        // chunk c covers f4-cols [w*16 + c*8, +8); lane handles f = q*32+l,
        // r = f>>3 (0..15), cc = f&7 (0..7).
        const float4* H4 = (t == 0)
            ? (const float4*)h0
            : (const float4*)(out + (size_t)(t - 1) * HDIM);
        const size_t rstride = (t == 0) ? 256u : (size_t)S_LEN * 256u;

        float4 va[4], vb[4];
#pragma unroll
        for (int q = 0; q < 4; q++) {          // chunk A loads
            int f = q * 32 + l, r = f >> 3, cc = f & 7;
            va[q] = __ldcv(&H4[(size_t)(b0g + r) * rstride + w * 16 + cc]);
        }
#pragma unroll
        for (int q = 0; q < 4; q++) {          // chunk B loads (in flight)
            int f = q * 32 + l, r = f >> 3, cc = f & 7;
            vb[q] = __ldcv(&H4[(size_t)(b0g + r) * rstride + w * 16 + 8 + cc]);
        }
#pragma unroll
        for (int q = 0; q < 4; q++) {          // STS chunk A
            int f = q * 32 + l, r = f >> 3, cc = f & 7;
            *(float4*)&hsm[r * WSTR + (w * 16 + cc) * 4] = va[q];
        }
        __syncwarp();

        // ---- dot on chunk A (kq 0..7) ----
        u64 acc[4][4];
#pragma unroll
        for (int m = 0; m < 4; m++)
#pragma unroll
            for (int i = 0; i < 4; i++) acc[m][i] = 0ull;

#pragma unroll
        for (int kq = 0; kq < 8; kq++) {
            ulonglong2 wv[4], hv[4];
#pragma unroll
            for (int i = 0; i < 4; i++) wv[i] = wp[i][kq];
#pragma unroll
            for (int m = 0; m < 4; m++) hv[m] = hp[m][kq];
#pragma unroll
            for (int m = 0; m < 4; m++)
#pragma unroll
                for (int i = 0; i < 4; i++) {
                    fma2(acc[m][i], wv[i].x, hv[m].x);
                    fma2(acc[m][i], wv[i].y, hv[m].y);
                }
        }

        // ---- STS chunk B, then dot chunk B (kq 8..15) ----
#pragma unroll
        for (int q = 0; q < 4; q++) {
            int f = q * 32 + l, r = f >> 3, cc = f & 7;
            *(float4*)&hsm[r * WSTR + (w * 16 + 8 + cc) * 4] = vb[q];
        }
        __syncwarp();

#pragma unroll
        for (int kq = 8; kq < 16; kq++) {
            ulonglong2 wv[4], hv[4];
#pragma unroll
            for (int i = 0; i < 4; i++) wv[i] = wp[i][kq];
#pragma unroll
            for (int m = 0; m < 4; m++) hv[m] = hp[m][kq];
#pragma unroll
            for (int m = 0; m < 4; m++)
#pragma unroll
                for (int i = 0; i < 4; i++) {
                    fma2(acc[m][i], wv[i].x, hv[m].x);
                    fma2(acc[m][i], wv[i].y, hv[m].y);
                }
        }

        // ---- partial reduction, two phases to fit SMEM ----
        // phase 1: warps 0-7 store into red[w]
        if (w < 8) {
            float* rw = red + w * RED_WSZ;
#pragma unroll
            for (int m = 0; m < 4; m++)
#pragma unroll
                for (int i = 0; i < 4; i++) {
                    float lo, hi;
                    unpack2(lo, hi, acc[m][i]);
                    rw[(bb + 4 * m) * RSTR + (jj + 8 * i)] = lo + hi;
                }
        }
        __syncthreads();
        // phase 2: warps 8-15 add into red[w-8]
        if (w >= 8) {
            float* rw = red + (w - 8) * RED_WSZ;
#pragma unroll
            for (int m = 0; m < 4; m++)
#pragma unroll
                for (int i = 0; i < 4; i++) {
                    float lo, hi;
                    unpack2(lo, hi, acc[m][i]);
                    int idx = (bb + 4 * m) * RSTR + (jj + 8 * i);
                    rw[idx] += lo + hi;
                }
        }
        __syncthreads();

        // ---- reduce 8 arrays + xp + relu; 1 output/thread, coalesced ----
        float s = xv;
#pragma unroll
        for (int ww = 0; ww < 8; ww++)
            s += red[ww * RED_WSZ + rb * RSTR + rj];
        float hvv = fmaxf(s, 0.0f);
        out[oxp] = hvv;
        if (t == S_LEN - 1) {
            out[OUT_TAIL + (size_t)bglob_r * HDIM + jglob_r] = hvv;
        }

        // ---- group barrier (32 CTAs), sense-reversing (proven), no sleep ----
        __syncthreads();
        if (tid == 0) {
            __threadfence();
            unsigned old = atomicAdd(&g_cnt[grp], 1u);
            if (old == 31u) {
                atomicExch(&g_cnt[grp], 0u);
                __threadfence();
                g_phase[grp] = my_phase ^ 1u;
            } else {
                while (g_phase[grp] == my_phase) { }
            }
            __threadfence();
        }
        my_phase ^= 1u;
        __syncthreads();
    }
}

// ====================================================================
// Launch
// ====================================================================
extern "C" void kernel_launch(void* const* d_in, const int* in_sizes, int n_in,
                              void* d_out, int out_size)
{
    const float* inputs = (const float*)d_in[0];   // [64,512,1024]
    const float* h0     = (const float*)d_in[1];   // [1,64,1024]
    const float* wih    = (const float*)d_in[2];   // [1024,1024]
    const float* whh    = (const float*)d_in[3];   // [1024,1024]
    const float* bih    = (const float*)d_in[4];   // [1024]
    const float* bhh    = (const float*)d_in[5];   // [1024]
    float* out = (float*)d_out;

    dim3 g1(HDIM / 128, M_TOT / 128);   // (8, 256)
    xproj_kernel<<<g1, 256>>>(inputs, wih, bih, bhh, out);

    cudaFuncSetAttribute(rec_kernel, cudaFuncAttributeMaxDynamicSharedMemorySize,
                         REC_SMEM_BYTES);
    rec_kernel<<<128, 512, REC_SMEM_BYTES>>>(h0, whh, out);
}